// round 7
// baseline (speedup 1.0000x reference)
#include <cuda_runtime.h>
#include <cuda_fp16.h>
#include <stdint.h>

#define NT    16384
#define DM    2048
#define NE    64
#define KC    32            // K per staged chunk (per K-group)
#define NCH   32            // chunks (2 groups x 32 x 32 = 2048)
#define TPC   64
#define WSTR  72            // W smem halves stride (row = 64 experts)
#define ASTR  40            // A smem halves stride (row = 32 k-halves)
#define LSTR  66

#define WBUF_BYTES (2 * 2 * KC * WSTR * 2)   // 18432 per buffer
#define A_OFF      (2 * WBUF_BYTES)          // 36864
#define A_BYTES    (2 * 2 * 64 * ASTR * 2)   // 20480
#define SMEM_DYN   (A_OFF + A_BYTES)         // 57344

// W split (fp16), k-major [DM][NE]; w0 = h(4096*w), w1 = h((4096w - w0)*4096)
__device__ __align__(16) __half g_w0[DM * NE];
__device__ __align__(16) __half g_w1[DM * NE];

__device__ __forceinline__ uint32_t smem_u32(const void* p) {
    uint32_t a;
    asm("{ .reg .u64 t; cvta.to.shared.u64 t, %1; cvt.u32.u64 %0, t; }" : "=r"(a) : "l"(p));
    return a;
}
__device__ __forceinline__ uint32_t h2u(__half2 h) {
    union { __half2 h; uint32_t u; } c; c.h = h; return c.u;
}
__device__ __forceinline__ void cpa16(uint32_t dst, const void* src) {
    asm volatile("cp.async.cg.shared.global [%0], [%1], 16;" :: "r"(dst), "l"(src));
}
__device__ __forceinline__ void ldmx4(uint32_t* r, uint32_t addr) {
    asm volatile("ldmatrix.sync.aligned.m8n8.x4.shared.b16 {%0,%1,%2,%3}, [%4];"
                 : "=r"(r[0]), "=r"(r[1]), "=r"(r[2]), "=r"(r[3]) : "r"(addr));
}
__device__ __forceinline__ void ldmx4t(uint32_t* r, uint32_t addr) {
    asm volatile("ldmatrix.sync.aligned.m8n8.x4.trans.shared.b16 {%0,%1,%2,%3}, [%4];"
                 : "=r"(r[0]), "=r"(r[1]), "=r"(r[2]), "=r"(r[3]) : "r"(addr));
}
__device__ __forceinline__ void mma16816(float* d,
        const uint32_t* a, uint32_t b0, uint32_t b1) {
    asm volatile("mma.sync.aligned.m16n8k16.row.col.f32.f16.f16.f32 "
                 "{%0,%1,%2,%3},{%4,%5,%6,%7},{%8,%9},{%0,%1,%2,%3};"
                 : "+f"(d[0]), "+f"(d[1]), "+f"(d[2]), "+f"(d[3])
                 : "r"(a[0]), "r"(a[1]), "r"(a[2]), "r"(a[3]), "r"(b0), "r"(b1));
}

// ---------------- prepass: split W ----------------
__global__ void wsplit(const float* __restrict__ W) {
    int i = blockIdx.x * 256 + threadIdx.x;
    float w = W[i] * 4096.0f;
    __half h0 = __float2half_rn(w);
    float r = (w - __half2float(h0)) * 4096.0f;
    g_w0[i] = h0;
    g_w1[i] = __float2half_rn(r);
}

// ---------------- main kernel ----------------
__global__ __launch_bounds__(256, 2)
void gating_mma(const float* __restrict__ x, const float* __restrict__ bias,
                float* __restrict__ out)
{
    extern __shared__ __align__(16) uint8_t smraw[];
    __shared__ float s_bias[NE];

    const int tid  = threadIdx.x;
    const int wid  = tid >> 5;
    const int lane = tid & 31;
    const int wg   = wid >> 2;          // K group
    const int w2   = (wid >> 1) & 1;    // token half (32)
    const int wn   = wid & 1;           // expert half (32)
    const int ct0  = blockIdx.x * TPC;

    if (tid < NE) s_bias[tid] = bias[tid];

    const uint32_t smb = smem_u32(smraw);

    // ---- staging thread-constants: f = j*256 + tid ----
    // x load:  grp = f>>9, row = (f>>3)&63, q = f&7  (float4 within 32-k row)
    const float* xsrc[4];
    uint32_t adst[4];
    int wgrp_c[4], wsplit_c[4], wkrow_c[4], wq_c[4];
    #pragma unroll
    for (int j = 0; j < 4; j++) {
        int f = j * 256 + tid;
        int grp = f >> 9, row = (f >> 3) & 63, q = f & 7;
        xsrc[j] = x + (size_t)(ct0 + row) * DM + grp * (DM / 2) + q * 4;
        adst[j] = smb + A_OFF + (uint32_t)(((grp * 2) * 64 + row) * ASTR + q * 4) * 2;
        // W cp.async: grp = f>>9, split = (f>>8)&1, krow = (f>>3)&31, q = f&7
        wgrp_c[j]  = f >> 9;
        wsplit_c[j]= (f >> 8) & 1;
        wkrow_c[j] = (f >> 3) & 31;
        wq_c[j]    = f & 7;
    }

    auto stageW = [&](int c, int buf) {
        #pragma unroll
        for (int j = 0; j < 4; j++) {
            const uint4* gp = wsplit_c[j] ? (const uint4*)g_w1 : (const uint4*)g_w0;
            const uint4* src = gp + (size_t)(wgrp_c[j] * (DM / 2) + c * KC + wkrow_c[j]) * 8 + wq_c[j];
            uint32_t dst = smb + buf * WBUF_BYTES
                + (uint32_t)(((wgrp_c[j] * 2 + wsplit_c[j]) * KC + wkrow_c[j]) * WSTR + wq_c[j] * 8) * 2;
            cpa16(dst, src);
        }
        asm volatile("cp.async.commit_group;" ::: "memory");
    };

    // ---- per-warp ldmatrix bases ----
    // A (non-trans): lane -> row (lane&15), col8 = (lane>>4)*8
    const uint32_t lmA = (uint32_t)((lane & 15) * ASTR + (lane >> 4) * 8) * 2;
    const uint32_t aB  = smb + A_OFF + (uint32_t)((wg * 2) * 64 + w2 * 32) * ASTR * 2 + lmA;
    // B (trans): k-row = (lane&7)+((lane>>3)&1)*8, n-col8 = (lane>>4)*8
    const uint32_t lmB = (uint32_t)((((lane & 7) + ((lane >> 3) & 1) * 8)) * WSTR
                                    + (lane >> 4) * 8 + wn * 32) * 2;
    const uint32_t bB  = smb + (uint32_t)((wg * 2) * KC * WSTR) * 2 + lmB;

    float acc1[2][4][4] = {}, acc2[2][4][4] = {};

    stageW(0, 0);
    float4 xf[4];
    #pragma unroll
    for (int j = 0; j < 4; j++) xf[j] = *(const float4*)xsrc[j];

    int buf = 0;
    for (int c = 0; c < NCH; ++c) {
        asm volatile("cp.async.wait_group 0;" ::: "memory");
        __syncthreads();                       // W_c ready; A_{c-1} reads done

        // ---- convert + STS A (both splits) ----
        #pragma unroll
        for (int j = 0; j < 4; j++) {
            float4 v = xf[j];
            __half2 h0a = __floats2half2_rn(v.x, v.y);
            __half2 h0b = __floats2half2_rn(v.z, v.w);
            float2 la = __half22float2(h0a), lb = __half22float2(h0b);
            __half2 h1a = __floats2half2_rn((v.x - la.x) * 4096.0f, (v.y - la.y) * 4096.0f);
            __half2 h1b = __floats2half2_rn((v.z - lb.x) * 4096.0f, (v.w - lb.y) * 4096.0f);
            asm volatile("st.shared.v2.b32 [%0], {%1,%2};"
                         :: "r"(adst[j]), "r"(h2u(h0a)), "r"(h2u(h0b)) : "memory");
            asm volatile("st.shared.v2.b32 [%0], {%1,%2};"
                         :: "r"(adst[j] + 64 * ASTR * 2), "r"(h2u(h1a)), "r"(h2u(h1b)) : "memory");
        }

        if (c + 1 < NCH) {
            stageW(c + 1, buf ^ 1);
            #pragma unroll
            for (int j = 0; j < 4; j++)
                xf[j] = *(const float4*)(xsrc[j] + (c + 1) * KC);
        }
        __syncthreads();                       // A_c visible

        const uint32_t bBuf = bB + buf * WBUF_BYTES;

        #pragma unroll
        for (int ks = 0; ks < 2; ++ks) {
            uint32_t a0[2][4], a1[2][4];
            #pragma unroll
            for (int mt = 0; mt < 2; mt++) {
                ldmx4(a0[mt], aB + (uint32_t)(mt * 16 * ASTR + ks * 16) * 2);
                ldmx4(a1[mt], aB + (uint32_t)(64 * ASTR + mt * 16 * ASTR + ks * 16) * 2);
            }
            #pragma unroll
            for (int p = 0; p < 2; p++) {
                uint32_t b0[4], b1[4];
                const uint32_t po = (uint32_t)(ks * 16 * WSTR + p * 16) * 2;
                ldmx4t(b0, bBuf + po);
                ldmx4t(b1, bBuf + (uint32_t)(KC * WSTR) * 2 + po);
                #pragma unroll
                for (int mt = 0; mt < 2; mt++) {
                    mma16816(acc1[mt][2*p],   a0[mt], b0[0], b0[1]);
                    mma16816(acc1[mt][2*p+1], a0[mt], b0[2], b0[3]);
                    mma16816(acc2[mt][2*p],   a0[mt], b1[0], b1[1]);
                    mma16816(acc2[mt][2*p+1], a0[mt], b1[2], b1[3]);
                    mma16816(acc2[mt][2*p],   a1[mt], b0[0], b0[1]);
                    mma16816(acc2[mt][2*p+1], a1[mt], b0[2], b0[3]);
                }
            }
        }
        buf ^= 1;
    }
    __syncthreads();   // all compute done before aliasing smem with partials

    // ---- partial logits: part[wg][token][expert] ----
    float* part = (float*)smraw;
    const float S2 = 1.0f / 4096.0f;
    const int gr = lane >> 2;
    const int gc = (lane & 3) * 2;
    #pragma unroll
    for (int mt = 0; mt < 2; mt++) {
        const int tl = w2 * 32 + mt * 16 + gr;
        #pragma unroll
        for (int nt = 0; nt < 4; nt++) {
            const int cc = wn * 32 + nt * 8 + gc;
            float p00 = acc1[mt][nt][0] + S2 * acc2[mt][nt][0];
            float p01 = acc1[mt][nt][1] + S2 * acc2[mt][nt][1];
            float p10 = acc1[mt][nt][2] + S2 * acc2[mt][nt][2];
            float p11 = acc1[mt][nt][3] + S2 * acc2[mt][nt][3];
            *(float2*)&part[(wg * TPC + tl)     * LSTR + cc] = make_float2(p00, p01);
            *(float2*)&part[(wg * TPC + tl + 8) * LSTR + cc] = make_float2(p10, p11);
        }
    }
    __syncthreads();

    // ---- per-token combine + softmax + top-2 ----
    if (tid < TPC) {
        const int t = ct0 + tid;
        float lg[NE];
        #pragma unroll
        for (int e = 0; e < NE; e++)
            lg[e] = (part[tid * LSTR + e] + part[(TPC + tid) * LSTR + e]) * S2 + s_bias[e];

        float m = lg[0];
        #pragma unroll
        for (int e = 1; e < NE; e++) m = fmaxf(m, lg[e]);

        float l1 = lg[0], l2 = -3.4e38f; int i1 = 0, i2 = 0;
        #pragma unroll
        for (int e = 1; e < NE; e++) {
            float vv = lg[e];
            if (vv > l1)      { l2 = l1; i2 = i1; l1 = vv; i1 = e; }
            else if (vv > l2) { l2 = vv; i2 = e; }
        }

        float s = 0.0f;
        #pragma unroll
        for (int e = 0; e < NE; e++) { float w = __expf(lg[e] - m); lg[e] = w; s += w; }
        float inv = 1.0f / s;

        float* out_w = out + (size_t)NT * 4 + (size_t)t * NE;
        #pragma unroll
        for (int e4 = 0; e4 < NE / 4; e4++) {
            float4 o4 = make_float4(lg[e4*4] * inv, lg[e4*4+1] * inv,
                                    lg[e4*4+2] * inv, lg[e4*4+3] * inv);
            *(float4*)(out_w + e4 * 4) = o4;
        }
        float w1 = __expf(l1 - m) * inv;
        float w2 = __expf(l2 - m) * inv;
        *(float2*)(out + (size_t)t * 2)                  = make_float2(w1, w2);
        *(float2*)(out + (size_t)NT * 2 + (size_t)t * 2) = make_float2((float)i1, (float)i2);
    }
}

extern "C" void kernel_launch(void* const* d_in, const int* in_sizes, int n_in,
                              void* d_out, int out_size)
{
    const float* x = (const float*)d_in[0];
    const float* W = (const float*)d_in[1];
    const float* b = (const float*)d_in[2];
    float* out = (float*)d_out;

    wsplit<<<(DM * NE) / 256, 256>>>(W);

    cudaFuncSetAttribute(gating_mma, cudaFuncAttributeMaxDynamicSharedMemorySize, SMEM_DYN);
    gating_mma<<<NT / TPC, 256, SMEM_DYN>>>(x, b, out);
}

// round 9
// speedup vs baseline: 1.4239x; 1.4239x over previous
#include <cuda_runtime.h>
#include <cuda_fp16.h>
#include <stdint.h>

#define NT    16384
#define DM    2048
#define NE    64
#define KC    128           // K per chunk
#define NCH   (DM / KC)     // 16 chunks
#define TPC   64
#define WSTR  72            // W smem halves stride (64 experts + 8 pad)
#define ASTR  136           // A smem halves stride (128 k + 8 pad)
#define LSTR  66            // logits smem float stride (MUST be even: float2 stores)

#define WBUF_BYTES (2 * KC * WSTR * 2)       // 36864 per buffer (2 splits)
#define A_OFF      (2 * WBUF_BYTES)          // 73728
#define A_BYTES    (2 * TPC * ASTR * 2)      // 34816
#define SMEM_DYN   (A_OFF + A_BYTES)         // 108544

// W split (fp16), k-major [DM][NE]; w0 = h(4096*w), w1 = h((4096w - w0)*4096)
__device__ __align__(16) __half g_w0[DM * NE];
__device__ __align__(16) __half g_w1[DM * NE];

__device__ __forceinline__ uint32_t smem_u32(const void* p) {
    uint32_t a;
    asm("{ .reg .u64 t; cvta.to.shared.u64 t, %1; cvt.u32.u64 %0, t; }" : "=r"(a) : "l"(p));
    return a;
}
__device__ __forceinline__ uint32_t h2u(__half2 h) {
    union { __half2 h; uint32_t u; } c; c.h = h; return c.u;
}
__device__ __forceinline__ void cpa16(uint32_t dst, const void* src) {
    asm volatile("cp.async.cg.shared.global [%0], [%1], 16;" :: "r"(dst), "l"(src));
}
__device__ __forceinline__ void ldmx4(uint32_t* r, uint32_t addr) {
    asm volatile("ldmatrix.sync.aligned.m8n8.x4.shared.b16 {%0,%1,%2,%3}, [%4];"
                 : "=r"(r[0]), "=r"(r[1]), "=r"(r[2]), "=r"(r[3]) : "r"(addr));
}
__device__ __forceinline__ void ldmx4t(uint32_t* r, uint32_t addr) {
    asm volatile("ldmatrix.sync.aligned.m8n8.x4.trans.shared.b16 {%0,%1,%2,%3}, [%4];"
                 : "=r"(r[0]), "=r"(r[1]), "=r"(r[2]), "=r"(r[3]) : "r"(addr));
}
__device__ __forceinline__ void mma16816(float* d,
        const uint32_t* a, uint32_t b0, uint32_t b1) {
    asm volatile("mma.sync.aligned.m16n8k16.row.col.f32.f16.f16.f32 "
                 "{%0,%1,%2,%3},{%4,%5,%6,%7},{%8,%9},{%0,%1,%2,%3};"
                 : "+f"(d[0]), "+f"(d[1]), "+f"(d[2]), "+f"(d[3])
                 : "r"(a[0]), "r"(a[1]), "r"(a[2]), "r"(a[3]), "r"(b0), "r"(b1));
}

// ---------------- prepass: split W ----------------
__global__ void wsplit(const float* __restrict__ W) {
    int i = blockIdx.x * 256 + threadIdx.x;
    float w = W[i] * 4096.0f;
    __half h0 = __float2half_rn(w);
    float r = (w - __half2float(h0)) * 4096.0f;
    g_w0[i] = h0;
    g_w1[i] = __float2half_rn(r);
}

// ---------------- main kernel ----------------
__global__ __launch_bounds__(256, 2)
void gating_mma(const float* __restrict__ x, const float* __restrict__ bias,
                float* __restrict__ out)
{
    extern __shared__ __align__(16) uint8_t smraw[];
    __shared__ float s_bias[NE];

    const int tid  = threadIdx.x;
    const int wid  = tid >> 5;
    const int lane = tid & 31;
    const int wm   = wid >> 1;          // token tile (16 tokens)
    const int wn   = wid & 1;           // expert half (32)
    const int ct0  = blockIdx.x * TPC;

    if (tid < NE) s_bias[tid] = bias[tid];

    const uint32_t smb = smem_u32(smraw);

    // ---- x staging map: per warp per j: one 64-token row slice, coalesced float4 ----
    const float* xrow = x + (size_t)(ct0 + (tid >> 5)) * DM + (size_t)(lane) * 4;
    const uint32_t a_st0 = smb + A_OFF + (uint32_t)(((tid >> 5)) * ASTR + lane * 4) * 2;

    // ---- W staging map: f = j*256 + tid; s = f>>10, krow = (f>>3)&127, q = f&7 ----
    auto stageW = [&](int c, int buf) {
        #pragma unroll
        for (int j = 0; j < 8; j++) {
            int f = j * 256 + tid;
            int s = f >> 10, krow = (f >> 3) & 127, q = f & 7;
            const uint4* gp = s ? (const uint4*)g_w1 : (const uint4*)g_w0;
            const uint4* src = gp + (size_t)(c * KC + krow) * 8 + q;
            uint32_t dst = smb + buf * WBUF_BYTES
                + (uint32_t)((s * KC + krow) * WSTR + q * 8) * 2;
            cpa16(dst, src);
        }
        asm volatile("cp.async.commit_group;" ::: "memory");
    };

    // ---- per-warp ldmatrix bases ----
    // A (non-trans): row = wm*16 + (lane&15), col8 = (lane>>4)*8
    const uint32_t aB = smb + A_OFF
        + (uint32_t)((wm * 16 + (lane & 15)) * ASTR + (lane >> 4) * 8) * 2;
    // B (trans): krow = (lane&7) + ((lane>>3)&1)*8 ; ncol = wn*32 + (lane>>4)*8
    const uint32_t bB0 = smb
        + (uint32_t)(((lane & 7) + ((lane >> 3) & 1) * 8) * WSTR
                     + wn * 32 + (lane >> 4) * 8) * 2;

    float acc1[4][4] = {}, acc2[4][4] = {};

    stageW(0, 0);
    float4 xf[8];
    #pragma unroll
    for (int j = 0; j < 8; j++)
        xf[j] = *(const float4*)(xrow + (size_t)(j * 8) * DM);

    int buf = 0;
    for (int c = 0; c < NCH; ++c) {
        asm volatile("cp.async.wait_group 0;" ::: "memory");
        __syncthreads();     // W(c) visible; all warps done with A(c-1)

        // ---- convert + STS A(c) (both splits), one row per warp per j ----
        #pragma unroll
        for (int j = 0; j < 8; j++) {
            float4 v = xf[j];
            __half2 h0a = __floats2half2_rn(v.x, v.y);
            __half2 h0b = __floats2half2_rn(v.z, v.w);
            float2 la = __half22float2(h0a), lb = __half22float2(h0b);
            __half2 h1a = __floats2half2_rn((v.x - la.x) * 4096.0f, (v.y - la.y) * 4096.0f);
            __half2 h1b = __floats2half2_rn((v.z - lb.x) * 4096.0f, (v.w - lb.y) * 4096.0f);
            uint32_t ad = a_st0 + (uint32_t)(j * 8 * ASTR) * 2;
            asm volatile("st.shared.v2.b32 [%0], {%1,%2};"
                         :: "r"(ad), "r"(h2u(h0a)), "r"(h2u(h0b)) : "memory");
            asm volatile("st.shared.v2.b32 [%0], {%1,%2};"
                         :: "r"(ad + (uint32_t)(TPC * ASTR) * 2),
                            "r"(h2u(h1a)), "r"(h2u(h1b)) : "memory");
        }

        if (c + 1 < NCH) {
            stageW(c + 1, buf ^ 1);
            #pragma unroll
            for (int j = 0; j < 8; j++)
                xf[j] = *(const float4*)(xrow + (size_t)(j * 8) * DM + (c + 1) * KC);
        }
        __syncthreads();     // A(c) visible

        const uint32_t bB = bB0 + buf * WBUF_BYTES;

        #pragma unroll
        for (int ks = 0; ks < KC / 16; ++ks) {
            uint32_t a0[4], a1[4];
            ldmx4(a0, aB + (uint32_t)(ks * 16) * 2);
            ldmx4(a1, aB + (uint32_t)(TPC * ASTR + ks * 16) * 2);
            #pragma unroll
            for (int p = 0; p < 2; p++) {
                uint32_t b0[4], b1[4];
                const uint32_t po = (uint32_t)(ks * 16 * WSTR + p * 16) * 2;
                ldmx4t(b0, bB + po);
                ldmx4t(b1, bB + (uint32_t)(KC * WSTR) * 2 + po);
                mma16816(acc1[2*p],   a0, b0[0], b0[1]);
                mma16816(acc1[2*p+1], a0, b0[2], b0[3]);
                mma16816(acc2[2*p],   a0, b1[0], b1[1]);
                mma16816(acc2[2*p+1], a0, b1[2], b1[3]);
                mma16816(acc2[2*p],   a1, b0[0], b0[1]);
                mma16816(acc2[2*p+1], a1, b0[2], b0[3]);
            }
        }
        buf ^= 1;
    }
    __syncthreads();   // all MMAs done before aliasing smem with logits

    // ---- logits to SMEM (alias W region): slog[token][expert] ----
    float* slog = (float*)smraw;
    const float S2 = 1.0f / 4096.0f;
    const int gr = lane >> 2;
    const int gc = (lane & 3) * 2;
    const int tl = wm * 16 + gr;
    #pragma unroll
    for (int nt = 0; nt < 4; nt++) {
        const int cc = wn * 32 + nt * 8 + gc;
        float p00 = acc1[nt][0] + S2 * acc2[nt][0];
        float p01 = acc1[nt][1] + S2 * acc2[nt][1];
        float p10 = acc1[nt][2] + S2 * acc2[nt][2];
        float p11 = acc1[nt][3] + S2 * acc2[nt][3];
        *(float2*)&slog[tl * LSTR + cc]       = make_float2(p00, p01);
        *(float2*)&slog[(tl + 8) * LSTR + cc] = make_float2(p10, p11);
    }
    __syncthreads();

    // ---- per-token softmax + top-2 (threads 0..63) ----
    if (tid < TPC) {
        const int t = ct0 + tid;
        float lg[NE];
        #pragma unroll
        for (int e = 0; e < NE; e++)
            lg[e] = slog[tid * LSTR + e] * S2 + s_bias[e];

        float m = lg[0];
        #pragma unroll
        for (int e = 1; e < NE; e++) m = fmaxf(m, lg[e]);

        float l1 = lg[0], l2 = -3.4e38f; int i1 = 0, i2 = 0;
        #pragma unroll
        for (int e = 1; e < NE; e++) {
            float vv = lg[e];
            if (vv > l1)      { l2 = l1; i2 = i1; l1 = vv; i1 = e; }
            else if (vv > l2) { l2 = vv; i2 = e; }
        }

        float s = 0.0f;
        #pragma unroll
        for (int e = 0; e < NE; e++) { float w = __expf(lg[e] - m); lg[e] = w; s += w; }
        float inv = 1.0f / s;

        float* out_w = out + (size_t)NT * 4 + (size_t)t * NE;
        #pragma unroll
        for (int e4 = 0; e4 < NE / 4; e4++) {
            float4 o4 = make_float4(lg[e4*4] * inv, lg[e4*4+1] * inv,
                                    lg[e4*4+2] * inv, lg[e4*4+3] * inv);
            *(float4*)(out_w + e4 * 4) = o4;
        }
        float w1 = __expf(l1 - m) * inv;
        float w2 = __expf(l2 - m) * inv;
        *(float2*)(out + (size_t)t * 2)                  = make_float2(w1, w2);
        *(float2*)(out + (size_t)NT * 2 + (size_t)t * 2) = make_float2((float)i1, (float)i2);
    }
}

extern "C" void kernel_launch(void* const* d_in, const int* in_sizes, int n_in,
                              void* d_out, int out_size)
{
    const float* x = (const float*)d_in[0];
    const float* W = (const float*)d_in[1];
    const float* b = (const float*)d_in[2];
    float* out = (float*)d_out;

    wsplit<<<(DM * NE) / 256, 256>>>(W);

    cudaFuncSetAttribute(gating_mma, cudaFuncAttributeMaxDynamicSharedMemorySize, SMEM_DYN);
    gating_mma<<<NT / TPC, 256, SMEM_DYN>>>(x, b, out);
}

// round 10
// speedup vs baseline: 1.4786x; 1.0385x over previous
#include <cuda_runtime.h>
#include <cuda_fp16.h>
#include <stdint.h>

#define NT    16384
#define DM    2048
#define NE    64
#define KC    64            // K per chunk
#define NCH   (DM / KC)     // 32 chunks
#define TPC   64
#define WSTR  72            // W smem halves stride (64 experts + 8 pad)
#define ASTR  72            // A smem halves stride (64 k + 8 pad)
#define LSTR  66            // logits smem float stride (even!)

#define WBUF  18432         // 2 splits x 64 k x 72 halves x 2B
#define ABUF  18432         // 2 splits x 64 tok x 72 halves x 2B
#define A_OFF (2 * WBUF)    // 36864
#define SMEM_DYN (A_OFF + 3 * ABUF)   // 92160

// W split (fp16), k-major [DM][NE]; w0 = h(4096*w), w1 = h((4096w - w0)*4096)
__device__ __align__(16) __half g_w0[DM * NE];
__device__ __align__(16) __half g_w1[DM * NE];

__device__ __forceinline__ uint32_t smem_u32(const void* p) {
    uint32_t a;
    asm("{ .reg .u64 t; cvta.to.shared.u64 t, %1; cvt.u32.u64 %0, t; }" : "=r"(a) : "l"(p));
    return a;
}
__device__ __forceinline__ uint32_t h2u(__half2 h) {
    union { __half2 h; uint32_t u; } c; c.h = h; return c.u;
}
__device__ __forceinline__ void cpa16(uint32_t dst, const void* src) {
    asm volatile("cp.async.cg.shared.global [%0], [%1], 16;" :: "r"(dst), "l"(src));
}
__device__ __forceinline__ void ldmx4(uint32_t* r, uint32_t addr) {
    asm volatile("ldmatrix.sync.aligned.m8n8.x4.shared.b16 {%0,%1,%2,%3}, [%4];"
                 : "=r"(r[0]), "=r"(r[1]), "=r"(r[2]), "=r"(r[3]) : "r"(addr));
}
__device__ __forceinline__ void ldmx4t(uint32_t* r, uint32_t addr) {
    asm volatile("ldmatrix.sync.aligned.m8n8.x4.trans.shared.b16 {%0,%1,%2,%3}, [%4];"
                 : "=r"(r[0]), "=r"(r[1]), "=r"(r[2]), "=r"(r[3]) : "r"(addr));
}
__device__ __forceinline__ void mma16816(float* d,
        const uint32_t* a, uint32_t b0, uint32_t b1) {
    asm volatile("mma.sync.aligned.m16n8k16.row.col.f32.f16.f16.f32 "
                 "{%0,%1,%2,%3},{%4,%5,%6,%7},{%8,%9},{%0,%1,%2,%3};"
                 : "+f"(d[0]), "+f"(d[1]), "+f"(d[2]), "+f"(d[3])
                 : "r"(a[0]), "r"(a[1]), "r"(a[2]), "r"(a[3]), "r"(b0), "r"(b1));
}

// ---------------- prepass: split W ----------------
__global__ void wsplit(const float* __restrict__ W) {
    int i = blockIdx.x * 256 + threadIdx.x;
    float w = W[i] * 4096.0f;
    __half h0 = __float2half_rn(w);
    float r = (w - __half2float(h0)) * 4096.0f;
    g_w0[i] = h0;
    g_w1[i] = __float2half_rn(r);
}

// ---------------- main kernel ----------------
__global__ __launch_bounds__(256, 2)
void gating_mma(const float* __restrict__ x, const float* __restrict__ bias,
                float* __restrict__ out)
{
    extern __shared__ __align__(16) uint8_t smraw[];
    __shared__ float s_bias[NE];

    const int tid  = threadIdx.x;
    const int wid  = tid >> 5;
    const int lane = tid & 31;
    const int wm   = wid >> 1;          // token tile (16 tokens)
    const int wn   = wid & 1;           // expert half (32)
    const int ct0  = blockIdx.x * TPC;

    if (tid < NE) s_bias[tid] = bias[tid];

    const uint32_t smb = smem_u32(smraw);

    // ---- x map: row_j = wid*2 + (lane>>4) + j*16, col float4 = lane&15 ----
    // per warp per j: 2 full 64-float rows -> 4 cache lines (optimal)
    const int xrow0 = wid * 2 + (lane >> 4);
    const float* xbase = x + (size_t)(ct0 + xrow0) * DM + (size_t)(lane & 15) * 4;
    const uint32_t a_st0 = smb + A_OFF
        + (uint32_t)(xrow0 * ASTR + (lane & 15) * 4) * 2;

    // ---- W staging: f = j*256 + tid; s=f>>9, krow=(f>>3)&63, q=f&7 ----
    auto stageW = [&](int c, int buf) {
        #pragma unroll
        for (int j = 0; j < 4; j++) {
            int f = j * 256 + tid;
            int s = f >> 9, krow = (f >> 3) & 63, q = f & 7;
            const uint4* gp = s ? (const uint4*)g_w1 : (const uint4*)g_w0;
            const uint4* src = gp + (size_t)(c * KC + krow) * 8 + q;
            uint32_t dst = smb + buf * WBUF
                + (uint32_t)((s * KC + krow) * WSTR + q * 8) * 2;
            cpa16(dst, src);
        }
        asm volatile("cp.async.commit_group;" ::: "memory");
    };

    float4 xf[4];
    auto loadX = [&](int c) {
        #pragma unroll
        for (int j = 0; j < 4; j++)
            xf[j] = *(const float4*)(xbase + (size_t)(j * 16) * DM + c * KC);
    };
    auto convA = [&](int bufidx) {
        const uint32_t ab = a_st0 + (uint32_t)bufidx * ABUF;
        #pragma unroll
        for (int j = 0; j < 4; j++) {
            float4 v = xf[j];
            __half2 h0a = __floats2half2_rn(v.x, v.y);
            __half2 h0b = __floats2half2_rn(v.z, v.w);
            float2 la = __half22float2(h0a), lb = __half22float2(h0b);
            __half2 h1a = __floats2half2_rn((v.x - la.x) * 4096.0f, (v.y - la.y) * 4096.0f);
            __half2 h1b = __floats2half2_rn((v.z - lb.x) * 4096.0f, (v.w - lb.y) * 4096.0f);
            uint32_t ad = ab + (uint32_t)(j * 16 * ASTR) * 2;
            asm volatile("st.shared.v2.b32 [%0], {%1,%2};"
                         :: "r"(ad), "r"(h2u(h0a)), "r"(h2u(h0b)) : "memory");
            asm volatile("st.shared.v2.b32 [%0], {%1,%2};"
                         :: "r"(ad + (uint32_t)(KC * ASTR) * 2),
                            "r"(h2u(h1a)), "r"(h2u(h1b)) : "memory");
        }
    };

    // ---- per-warp ldmatrix bases ----
    // A (non-trans): row = wm*16 + (lane&15), col8 = (lane>>4)*8
    const uint32_t aB0 = smb + A_OFF
        + (uint32_t)((wm * 16 + (lane & 15)) * ASTR + (lane >> 4) * 8) * 2;
    // B (trans): krow = (lane&7)+((lane>>3)&1)*8; ncol = wn*32 + (lane>>4)*8
    const uint32_t bB0 = smb
        + (uint32_t)(((lane & 7) + ((lane >> 3) & 1) * 8) * WSTR
                     + wn * 32 + (lane >> 4) * 8) * 2;

    float acc1[4][4] = {}, acc2[4][4] = {};

    // ---- prologue ----
    stageW(0, 0);
    loadX(0);
    convA(0);
    loadX(1);

    for (int c = 0; c < NCH; ++c) {
        asm volatile("cp.async.wait_group 0;" ::: "memory");
        __syncthreads();   // W(c) + A(c) visible; A((c+1)%3) readers done

        if (c + 1 < NCH) stageW(c + 1, (c + 1) & 1);

        const uint32_t aB = aB0 + (uint32_t)(c % 3) * ABUF;
        const uint32_t bB = bB0 + (uint32_t)(c & 1) * WBUF;

        #pragma unroll
        for (int ks = 0; ks < KC / 16; ++ks) {
            uint32_t a0[4], a1[4], b00[4], b01[4], b10[4], b11[4];
            ldmx4 (a0,  aB + (uint32_t)(ks * 16) * 2);
            ldmx4 (a1,  aB + (uint32_t)(KC * ASTR + ks * 16) * 2);
            const uint32_t ko = (uint32_t)(ks * 16 * WSTR) * 2;
            ldmx4t(b00, bB + ko);
            ldmx4t(b01, bB + ko + 32);
            ldmx4t(b10, bB + (uint32_t)(KC * WSTR) * 2 + ko);
            ldmx4t(b11, bB + (uint32_t)(KC * WSTR) * 2 + ko + 32);
            // distance-4 accumulator reuse
            mma16816(acc1[0], a0, b00[0], b00[1]);
            mma16816(acc1[1], a0, b00[2], b00[3]);
            mma16816(acc1[2], a0, b01[0], b01[1]);
            mma16816(acc1[3], a0, b01[2], b01[3]);
            mma16816(acc2[0], a0, b10[0], b10[1]);
            mma16816(acc2[1], a0, b10[2], b10[3]);
            mma16816(acc2[2], a0, b11[0], b11[1]);
            mma16816(acc2[3], a0, b11[2], b11[3]);
            mma16816(acc2[0], a1, b00[0], b00[1]);
            mma16816(acc2[1], a1, b00[2], b00[3]);
            mma16816(acc2[2], a1, b01[0], b01[1]);
            mma16816(acc2[3], a1, b01[2], b01[3]);
        }

        // convert next chunk's A in the MMA shadow
        if (c + 1 < NCH) {
            convA((c + 1) % 3);
            if (c + 2 < NCH) loadX(c + 2);
        }
    }
    __syncthreads();   // all MMAs done before aliasing smem with logits

    // ---- logits to SMEM (alias): slog[token][expert] ----
    float* slog = (float*)smraw;
    const float S2 = 1.0f / 4096.0f;
    const int gr = lane >> 2;
    const int gc = (lane & 3) * 2;
    const int tl = wm * 16 + gr;
    #pragma unroll
    for (int nt = 0; nt < 4; nt++) {
        const int cc = wn * 32 + nt * 8 + gc;
        float p00 = acc1[nt][0] + S2 * acc2[nt][0];
        float p01 = acc1[nt][1] + S2 * acc2[nt][1];
        float p10 = acc1[nt][2] + S2 * acc2[nt][2];
        float p11 = acc1[nt][3] + S2 * acc2[nt][3];
        *(float2*)&slog[tl * LSTR + cc]       = make_float2(p00, p01);
        *(float2*)&slog[(tl + 8) * LSTR + cc] = make_float2(p10, p11);
    }
    __syncthreads();

    // ---- per-token softmax + top-2 (threads 0..63) ----
    if (tid < TPC) {
        const int t = ct0 + tid;
        float lg[NE];
        #pragma unroll
        for (int e = 0; e < NE; e++)
            lg[e] = slog[tid * LSTR + e] * S2 + s_bias[e];

        float m = lg[0];
        #pragma unroll
        for (int e = 1; e < NE; e++) m = fmaxf(m, lg[e]);

        float l1 = lg[0], l2 = -3.4e38f; int i1 = 0, i2 = 0;
        #pragma unroll
        for (int e = 1; e < NE; e++) {
            float vv = lg[e];
            if (vv > l1)      { l2 = l1; i2 = i1; l1 = vv; i1 = e; }
            else if (vv > l2) { l2 = vv; i2 = e; }
        }

        float s = 0.0f;
        #pragma unroll
        for (int e = 0; e < NE; e++) { float w = __expf(lg[e] - m); lg[e] = w; s += w; }
        float inv = 1.0f / s;

        float* out_w = out + (size_t)NT * 4 + (size_t)t * NE;
        #pragma unroll
        for (int e4 = 0; e4 < NE / 4; e4++) {
            float4 o4 = make_float4(lg[e4*4] * inv, lg[e4*4+1] * inv,
                                    lg[e4*4+2] * inv, lg[e4*4+3] * inv);
            *(float4*)(out_w + e4 * 4) = o4;
        }
        float w1 = __expf(l1 - m) * inv;
        float w2 = __expf(l2 - m) * inv;
        *(float2*)(out + (size_t)t * 2)                  = make_float2(w1, w2);
        *(float2*)(out + (size_t)NT * 2 + (size_t)t * 2) = make_float2((float)i1, (float)i2);
    }
}

extern "C" void kernel_launch(void* const* d_in, const int* in_sizes, int n_in,
                              void* d_out, int out_size)
{
    const float* x = (const float*)d_in[0];
    const float* W = (const float*)d_in[1];
    const float* b = (const float*)d_in[2];
    float* out = (float*)d_out;

    wsplit<<<(DM * NE) / 256, 256>>>(W);

    cudaFuncSetAttribute(gating_mma, cudaFuncAttributeMaxDynamicSharedMemorySize, SMEM_DYN);
    gating_mma<<<NT / TPC, 256, SMEM_DYN>>>(x, b, out);
}

// round 12
// speedup vs baseline: 1.5242x; 1.0308x over previous
#include <cuda_runtime.h>
#include <cuda_fp16.h>
#include <stdint.h>

#define NT    16384
#define DM    2048
#define NE    64
#define KC    64            // K per chunk
#define NCH   (DM / KC)     // 32 chunks
#define TPC   64
#define WSTR  72            // W smem halves stride
#define ASTR  72            // A smem halves stride
#define LSTR  66            // logits smem float stride (even)

#define WBUF  (2 * KC * WSTR * 2)     // 18432
#define ABUF  (2 * TPC * ASTR * 2)    // 18432
#define A_OFF (2 * WBUF)              // 36864
#define SMEM_DYN (A_OFF + 2 * ABUF)   // 73728

// W split (fp16), k-major [DM][NE]; w' = 4096w; w0 = h(w'), w1 = h((w'-w0)*4096)
__device__ __align__(16) __half g_w0[DM * NE];
__device__ __align__(16) __half g_w1[DM * NE];

__device__ __forceinline__ uint32_t smem_u32(const void* p) {
    uint32_t a;
    asm("{ .reg .u64 t; cvta.to.shared.u64 t, %1; cvt.u32.u64 %0, t; }" : "=r"(a) : "l"(p));
    return a;
}
__device__ __forceinline__ uint32_t h2u(__half2 h) {
    union { __half2 h; uint32_t u; } c; c.h = h; return c.u;
}
__device__ __forceinline__ void cpa16(uint32_t dst, const void* src) {
    asm volatile("cp.async.cg.shared.global [%0], [%1], 16;" :: "r"(dst), "l"(src));
}
__device__ __forceinline__ void ldmx4(uint32_t* r, uint32_t addr) {
    asm volatile("ldmatrix.sync.aligned.m8n8.x4.shared.b16 {%0,%1,%2,%3}, [%4];"
                 : "=r"(r[0]), "=r"(r[1]), "=r"(r[2]), "=r"(r[3]) : "r"(addr));
}
__device__ __forceinline__ void ldmx4t(uint32_t* r, uint32_t addr) {
    asm volatile("ldmatrix.sync.aligned.m8n8.x4.trans.shared.b16 {%0,%1,%2,%3}, [%4];"
                 : "=r"(r[0]), "=r"(r[1]), "=r"(r[2]), "=r"(r[3]) : "r"(addr));
}
__device__ __forceinline__ void mma16816(float* d,
        const uint32_t* a, uint32_t b0, uint32_t b1) {
    asm volatile("mma.sync.aligned.m16n8k16.row.col.f32.f16.f16.f32 "
                 "{%0,%1,%2,%3},{%4,%5,%6,%7},{%8,%9},{%0,%1,%2,%3};"
                 : "+f"(d[0]), "+f"(d[1]), "+f"(d[2]), "+f"(d[3])
                 : "r"(a[0]), "r"(a[1]), "r"(a[2]), "r"(a[3]), "r"(b0), "r"(b1));
}

// ---------------- prepass: split W (round-10 math) ----------------
__global__ void wsplit(const float* __restrict__ W) {
    int i = blockIdx.x * 256 + threadIdx.x;
    float w = W[i] * 4096.0f;
    __half h0 = __float2half_rn(w);
    float r = (w - __half2float(h0)) * 4096.0f;
    g_w0[i] = h0;
    g_w1[i] = __float2half_rn(r);
}

// ---------------- main kernel ----------------
__global__ __launch_bounds__(128, 3)
void gating_mma(const float* __restrict__ x, const float* __restrict__ bias,
                float* __restrict__ out)
{
    extern __shared__ __align__(16) uint8_t smraw[];
    __shared__ float s_bias[NE];

    const int tid  = threadIdx.x;
    const int wid  = tid >> 5;
    const int lane = tid & 31;
    const int wm   = wid >> 1;          // token 32-tile
    const int wn   = wid & 1;           // expert half (32)
    const int ct0  = blockIdx.x * TPC;

    if (tid < NE) s_bias[tid] = bias[tid];

    const uint32_t smb = smem_u32(smraw);

    // ---- x map: row = j*8 + (tid>>4), q = tid&15 (coalesced float4) ----
    const int xrow0 = tid >> 4;
    const int xq    = tid & 15;
    const float* xbase = x + (size_t)(ct0 + xrow0) * DM + (size_t)xq * 4;
    const uint32_t a_st0 = smb + A_OFF + (uint32_t)(xrow0 * ASTR + xq * 4) * 2;

    // ---- W staging: f = j*128 + tid; s = f>>9, krow = (f>>3)&63, q = f&7 ----
    auto stageW = [&](int c, int buf) {
        #pragma unroll
        for (int j = 0; j < 8; j++) {
            int f = j * 128 + tid;
            int s = f >> 9, krow = (f >> 3) & 63, q = f & 7;
            const uint4* gp = s ? (const uint4*)g_w1 : (const uint4*)g_w0;
            const uint4* src = gp + (size_t)(c * KC + krow) * 8 + q;
            uint32_t dst = smb + buf * WBUF
                + (uint32_t)((s * KC + krow) * WSTR + q * 8) * 2;
            cpa16(dst, src);
        }
        asm volatile("cp.async.commit_group;" ::: "memory");
    };

    float4 xf[8];
    auto loadX = [&](int c) {
        #pragma unroll
        for (int j = 0; j < 8; j++)
            xf[j] = *(const float4*)(xbase + (size_t)(j * 8) * DM + c * KC);
    };
    // x0 = h(x); x1 = h((x - x0)*4096)   [scaled residual: round 4-10 proven]
    auto convA = [&](int bufidx) {
        const uint32_t ab = a_st0 + (uint32_t)bufidx * ABUF;
        #pragma unroll
        for (int j = 0; j < 8; j++) {
            float4 v = xf[j];
            __half2 h0a = __floats2half2_rn(v.x, v.y);
            __half2 h0b = __floats2half2_rn(v.z, v.w);
            float2 la = __half22float2(h0a), lb = __half22float2(h0b);
            __half2 h1a = __floats2half2_rn((v.x - la.x) * 4096.0f, (v.y - la.y) * 4096.0f);
            __half2 h1b = __floats2half2_rn((v.z - lb.x) * 4096.0f, (v.w - lb.y) * 4096.0f);
            uint32_t ad = ab + (uint32_t)(j * 8 * ASTR) * 2;
            asm volatile("st.shared.v2.b32 [%0], {%1,%2};"
                         :: "r"(ad), "r"(h2u(h0a)), "r"(h2u(h0b)) : "memory");
            asm volatile("st.shared.v2.b32 [%0], {%1,%2};"
                         :: "r"(ad + (uint32_t)(TPC * ASTR) * 2),
                            "r"(h2u(h1a)), "r"(h2u(h1b)) : "memory");
        }
    };

    // ---- per-warp ldmatrix bases ----
    const uint32_t aB0 = smb + A_OFF
        + (uint32_t)((wm * 32 + (lane & 15)) * ASTR + (lane >> 4) * 8) * 2;
    const uint32_t bB0 = smb
        + (uint32_t)(((lane & 7) + ((lane >> 3) & 1) * 8) * WSTR
                     + wn * 32 + (lane >> 4) * 8) * 2;

    float acc1[2][4][4] = {}, acc2[2][4][4] = {};

    // ---- prologue ----
    stageW(0, 0);
    loadX(0);
    convA(0);
    loadX(1);

    for (int c = 0; c < NCH; ++c) {
        asm volatile("cp.async.wait_group 0;" ::: "memory");
        __syncthreads();   // W(c) + A(c) visible; A(c-1) readers retired

        if (c + 1 < NCH) stageW(c + 1, (c + 1) & 1);

        const uint32_t aB = aB0 + (uint32_t)(c & 1) * ABUF;
        const uint32_t bB = bB0 + (uint32_t)(c & 1) * WBUF;

        #pragma unroll
        for (int ks = 0; ks < KC / 16; ++ks) {
            uint32_t a0[2][4], a1[2][4];       // [mt]
            uint32_t b0[2][4], b1[2][4];       // [p]
            const uint32_t ao = (uint32_t)(ks * 16) * 2;
            ldmx4(a0[0], aB + ao);
            ldmx4(a0[1], aB + ao + (uint32_t)(16 * ASTR) * 2);
            ldmx4(a1[0], aB + ao + (uint32_t)(TPC * ASTR) * 2);
            ldmx4(a1[1], aB + ao + (uint32_t)((TPC + 16) * ASTR) * 2);
            const uint32_t ko = (uint32_t)(ks * 16 * WSTR) * 2;
            ldmx4t(b0[0], bB + ko);
            ldmx4t(b0[1], bB + ko + 32);
            ldmx4t(b1[0], bB + (uint32_t)(KC * WSTR) * 2 + ko);
            ldmx4t(b1[1], bB + (uint32_t)(KC * WSTR) * 2 + ko + 32);

            // x0*w0 -> acc1 (8), then x0*w1 -> acc2 (8), then x1*w0 -> acc2 (8)
            #pragma unroll
            for (int mt = 0; mt < 2; mt++) {
                mma16816(acc1[mt][0], a0[mt], b0[0][0], b0[0][1]);
                mma16816(acc1[mt][1], a0[mt], b0[0][2], b0[0][3]);
                mma16816(acc1[mt][2], a0[mt], b0[1][0], b0[1][1]);
                mma16816(acc1[mt][3], a0[mt], b0[1][2], b0[1][3]);
            }
            #pragma unroll
            for (int mt = 0; mt < 2; mt++) {
                mma16816(acc2[mt][0], a0[mt], b1[0][0], b1[0][1]);
                mma16816(acc2[mt][1], a0[mt], b1[0][2], b1[0][3]);
                mma16816(acc2[mt][2], a0[mt], b1[1][0], b1[1][1]);
                mma16816(acc2[mt][3], a0[mt], b1[1][2], b1[1][3]);
            }
            #pragma unroll
            for (int mt = 0; mt < 2; mt++) {
                mma16816(acc2[mt][0], a1[mt], b0[0][0], b0[0][1]);
                mma16816(acc2[mt][1], a1[mt], b0[0][2], b0[0][3]);
                mma16816(acc2[mt][2], a1[mt], b0[1][0], b0[1][1]);
                mma16816(acc2[mt][3], a1[mt], b0[1][2], b0[1][3]);
            }
        }

        // convert next chunk's A in the MMA shadow
        if (c + 1 < NCH) {
            convA((c + 1) & 1);
            if (c + 2 < NCH) loadX(c + 2);
        }
    }
    __syncthreads();

    // ---- logits to SMEM (alias W region) ----
    float* slog = (float*)smraw;
    const float S2 = 1.0f / 4096.0f;
    const int gr = lane >> 2;
    const int gc = (lane & 3) * 2;
    #pragma unroll
    for (int mt = 0; mt < 2; mt++) {
        const int tl = wm * 32 + mt * 16 + gr;
        #pragma unroll
        for (int nt = 0; nt < 4; nt++) {
            const int cc = wn * 32 + nt * 8 + gc;
            float p00 = acc1[mt][nt][0] + S2 * acc2[mt][nt][0];
            float p01 = acc1[mt][nt][1] + S2 * acc2[mt][nt][1];
            float p10 = acc1[mt][nt][2] + S2 * acc2[mt][nt][2];
            float p11 = acc1[mt][nt][3] + S2 * acc2[mt][nt][3];
            *(float2*)&slog[tl * LSTR + cc]       = make_float2(p00, p01);
            *(float2*)&slog[(tl + 8) * LSTR + cc] = make_float2(p10, p11);
        }
    }
    __syncthreads();

    // ---- per-token softmax + top-2 (threads 0..63) ----
    if (tid < TPC) {
        const int t = ct0 + tid;
        float lg[NE];
        #pragma unroll
        for (int e = 0; e < NE; e++)
            lg[e] = slog[tid * LSTR + e] * S2 + s_bias[e];

        float m = lg[0];
        #pragma unroll
        for (int e = 1; e < NE; e++) m = fmaxf(m, lg[e]);

        float l1 = lg[0], l2 = -3.4e38f; int i1 = 0, i2 = 0;
        #pragma unroll
        for (int e = 1; e < NE; e++) {
            float vv = lg[e];
            if (vv > l1)      { l2 = l1; i2 = i1; l1 = vv; i1 = e; }
            else if (vv > l2) { l2 = vv; i2 = e; }
        }

        float s = 0.0f;
        #pragma unroll
        for (int e = 0; e < NE; e++) { float w = __expf(lg[e] - m); lg[e] = w; s += w; }
        float inv = 1.0f / s;

        float* out_w = out + (size_t)NT * 4 + (size_t)t * NE;
        #pragma unroll
        for (int e4 = 0; e4 < NE / 4; e4++) {
            float4 o4 = make_float4(lg[e4*4] * inv, lg[e4*4+1] * inv,
                                    lg[e4*4+2] * inv, lg[e4*4+3] * inv);
            *(float4*)(out_w + e4 * 4) = o4;
        }
        float w1 = __expf(l1 - m) * inv;
        float w2 = __expf(l2 - m) * inv;
        *(float2*)(out + (size_t)t * 2)                  = make_float2(w1, w2);
        *(float2*)(out + (size_t)NT * 2 + (size_t)t * 2) = make_float2((float)i1, (float)i2);
    }
}

extern "C" void kernel_launch(void* const* d_in, const int* in_sizes, int n_in,
                              void* d_out, int out_size)
{
    const float* x = (const float*)d_in[0];
    const float* W = (const float*)d_in[1];
    const float* b = (const float*)d_in[2];
    float* out = (float*)d_out;

    wsplit<<<(DM * NE) / 256, 256>>>(W);

    cudaFuncSetAttribute(gating_mma, cudaFuncAttributeMaxDynamicSharedMemorySize, SMEM_DYN);
    gating_mma<<<NT / TPC, 128, SMEM_DYN>>>(x, b, out);
}